// round 11
// baseline (speedup 1.0000x reference)
#include <cuda_runtime.h>
#include <math.h>

// ---------------- problem constants ----------------
#define B_ 16
#define T_ 2048
#define H_ 1024
#define H4 (H_ / 4)      // 256 float4 per row
#define BT 32            // timesteps per alphas block
#define NCHUNK (T_ / BT) // 64 alphas blocks per batch
#define NS B_            // dedicated scan blocks (bids 0..15)
#define NA (B_ * NCHUNK) // 1024 alphas blocks
#define RPB 8            // output rows per gather block

// ---------------- device scratch (no allocations allowed) ----------------
__device__ float g_alphas[B_ * T_];
__device__ float g_dist[B_ * T_];
__device__ float g_rem[B_ * T_];
__device__ int   g_fire_t[B_ * T_];
__device__ int   g_nf[B_];
__device__ int   g_aflag[NA];   // per-chunk alphas-done flags (b*64+c)
__device__ int   g_sflag[B_];   // scan-done flags
__device__ float g_dummy_len[B_];
__device__ float g_dummy_fires[B_ * T_];

// ---------------- init: reset flags each call ------------------------------
__global__ void init_kernel() {
    const int i = blockIdx.x * blockDim.x + threadIdx.x;
    if (i < NA) g_aflag[i] = 0;
    if (i < B_) g_sflag[i] = 0;
}

// ---------------- alphas math helper ----------------
__device__ __forceinline__ float part1(float xm, float x0, float xp,
                                       float w0, float w1, float w2,
                                       float cb, float lw) {
    float v = fmaf(w0, xm, fmaf(w1, x0, fmaf(w2, xp, cb)));
    v += x0;                 // residual
    v = fmaxf(v, 0.0f);      // relu
    return lw * v;
}

// ---------------- fused kernel ---------------------------------------------
// bids [0,16)        : scan block for batch b=bid; consumes per-chunk flags.
// bids [16,16+1024)  : alphas, batch-major (ab=bid-16, b=ab/64, c=ab%64).
// bids [.., +16*gbl) : gather, batch-major; waits on per-batch scan flag.
__global__ __launch_bounds__(256) void fused_kernel(
    const float* __restrict__ hidden, const float* __restrict__ conv_w,
    const float* __restrict__ conv_b, const float* __restrict__ lin_w,
    const float* __restrict__ lin_b,
    float* __restrict__ out_cif, float* __restrict__ out_len,
    float* __restrict__ out_fires, int L, int gblocks)
{
    // scan staging (idle for alphas/gather roles): 4*T_*4 = 32KB
    __shared__ float s_f[T_];
    __shared__ float s_d[T_];
    __shared__ float s_r[T_];
    __shared__ int   s_t[T_];
    __shared__ int   s_misc[48];
    __shared__ float s_fmisc[48];   // alphas wpart = 32 floats

    const int bid = blockIdx.x;
    const int tid = threadIdx.x;

    if (bid < NS) {
        // ================== SCAN (incremental consumer) ==================
        const int b = bid;
        const int bT = b * T_;
        if (tid == 0) {
            float integ = 0.0f;
            int nf = 0;
            const int fbase = b * NCHUNK;
            for (int c = 0; c < NCHUNK; ++c) {
                while (__ldcg(&g_aflag[fbase + c]) == 0) __nanosleep(64);
                __threadfence();                 // acquire
                const float4* ap = (const float4*)(g_alphas + bT + c * BT);
                float4 av4[BT / 4];
#pragma unroll
                for (int i = 0; i < BT / 4; ++i) av4[i] = __ldcg(ap + i);
                const float* a = (const float*)av4;
                const int tbase = c * BT;
#pragma unroll
                for (int j = 0; j < BT; ++j) {
                    const float aj = a[j];
                    const float t1 = integ + aj;     // fires (pre-subtract)
                    const float dist = 1.0f - integ; // distribution completion
                    const float t2 = t1 - 1.0f;      // exact on [1,2) (Sterbenz)
                    const bool fire = (t1 >= 1.0f);
                    s_f[tbase + j] = t1;
                    s_d[tbase + j] = dist;
                    s_r[tbase + j] = aj - dist;
                    s_t[nf] = tbase + j;             // kept iff fire
                    nf += fire ? 1 : 0;
                    integ = fire ? t2 : t1;
                }
            }
            s_misc[1] = nf;
            g_nf[b] = nf;
            out_len[b] = integ + (float)nf;          // == fp-sum of alphas
        }
        __syncthreads();

        const int nf = s_misc[1];
        for (int i = tid; i < T_; i += 256) {
            out_fires[bT + i] = s_f[i];
            g_dist[bT + i]    = s_d[i];
            g_rem[bT + i]     = s_r[i];
        }
        for (int i = tid; i < nf; i += 256)
            g_fire_t[bT + i] = s_t[i];
        __threadfence();                             // release scan results
        __syncthreads();
        if (tid == 0) atomicExch(&g_sflag[b], 1);
    } else if (bid < NS + NA) {
        // ======================= ALPHAS (R6 body) =======================
        const int ab = bid - NS;
        const int b = ab >> 6;              // batch-major: batch 0 first
        const int tstart = (ab & 63) * BT;
        const int lane = tid & 31;
        const int warp = tid >> 5;
        float (*wpart)[8] = (float (*)[8])s_fmisc;   // [4][8] = 32 floats

        const int h0 = tid * 4;
        float w0[4], w1[4], w2[4], cb[4], lw[4];
#pragma unroll
        for (int j = 0; j < 4; j++) {
            w0[j] = conv_w[(h0 + j) * 3 + 0];
            w1[j] = conv_w[(h0 + j) * 3 + 1];
            w2[j] = conv_w[(h0 + j) * 3 + 2];
            cb[j] = conv_b[h0 + j];
            lw[j] = lin_w[h0 + j];
        }
        const float lb = lin_b[0];

        const float4* Hb = (const float4*)hidden + (size_t)b * T_ * H4;
        const float4 z4 = make_float4(0.f, 0.f, 0.f, 0.f);

        float4 xm = (tstart > 0) ? Hb[(size_t)(tstart - 1) * H4 + tid] : z4;
        float4 x0 = Hb[(size_t)tstart * H4 + tid];

        for (int c = 0; c < BT / 4; ++c) {
            const int t0 = tstart + c * 4;
            float4 xA = Hb[(size_t)(t0 + 1) * H4 + tid];
            float4 xB = Hb[(size_t)(t0 + 2) * H4 + tid];
            float4 xC = Hb[(size_t)(t0 + 3) * H4 + tid];
            float4 xD = (t0 + 4 < T_) ? Hb[(size_t)(t0 + 4) * H4 + tid] : z4;

            float s[4];
            {
                const float4* P[6] = { &xm, &x0, &xA, &xB, &xC, &xD };
#pragma unroll
                for (int i = 0; i < 4; i++) {
                    const float4 a = *P[i], m = *P[i + 1], p = *P[i + 2];
                    float acc;
                    acc  = part1(a.x, m.x, p.x, w0[0], w1[0], w2[0], cb[0], lw[0]);
                    acc += part1(a.y, m.y, p.y, w0[1], w1[1], w2[1], cb[1], lw[1]);
                    acc += part1(a.z, m.z, p.z, w0[2], w1[2], w2[2], cb[2], lw[2]);
                    acc += part1(a.w, m.w, p.w, w0[3], w1[3], w2[3], cb[3], lw[3]);
                    s[i] = acc;
                }
            }
#pragma unroll
            for (int i = 0; i < 4; i++) {
#pragma unroll
                for (int off = 16; off; off >>= 1)
                    s[i] += __shfl_xor_sync(0xffffffffu, s[i], off);
            }
            if (lane == 0) {
#pragma unroll
                for (int i = 0; i < 4; i++) wpart[i][warp] = s[i];
            }
            __syncthreads();
            if (tid < 4) {
                float tot = lb;
#pragma unroll
                for (int w = 0; w < 8; w++) tot += wpart[tid][w];
                g_alphas[b * T_ + t0 + tid] = 1.0f / (1.0f + expf(-tot));
            }
            __syncthreads();
            xm = xC;
            x0 = xD;
        }
        __threadfence();                 // release this chunk's alphas
        __syncthreads();
        if (tid == 0) atomicExch(&g_aflag[ab], 1);
    } else {
        // ======================= GATHER (R10 body) ======================
        const int idx = bid - NS - NA;
        const int b = idx / gblocks;     // batch-major
        const int r0 = (idx - b * gblocks) * RPB;

        if (tid == 0) {                  // wait for this batch's scan
            while (__ldcg(&g_sflag[b]) == 0) __nanosleep(128);
        }
        __syncthreads();
        __threadfence();

        int*   s_ft   = s_misc + 8;      // [RPB]
        float* s_dist = s_fmisc;         // [RPB]
        float* s_rem  = s_fmisc + RPB;   // [RPB]

        const int nf = __ldcg(&g_nf[b]);
        const int bT = b * T_;
        const int rlim = min(L, r0 + RPB);
        const int rend = min(nf, rlim);
        const int nr = rend - r0;

        if (tid < RPB && tid < nr) {
            const int ft = __ldcg(&g_fire_t[bT + r0 + tid]);
            s_ft[tid]   = ft;
            s_dist[tid] = __ldcg(&g_dist[bT + ft]);
            s_rem[tid]  = __ldcg(&g_rem[bT + ft]);
        }
        if (tid == 0) {
            if (r0 > 0 && nr > 0) {
                const int tp = __ldcg(&g_fire_t[bT + r0 - 1]);
                s_misc[1] = tp;
                s_fmisc[2 * RPB] = __ldcg(&g_rem[bT + tp]);
            } else {
                s_misc[1] = -1;
                s_fmisc[2 * RPB] = 0.0f;
            }
        }
        __syncthreads();
        const int   tprev   = s_misc[1];
        const float remprev = s_fmisc[2 * RPB];

        const float4* Hb = (const float4*)hidden + (size_t)b * T_ * H4;
        float4* Ob = (float4*)out_cif + (size_t)b * L * H4;

        if (nr > 0) {
            float4 acc = make_float4(0.f, 0.f, 0.f, 0.f);
            int ts = 0;
            if (tprev >= 0) {
                const float rp = remprev;
                const float4 h = __ldg(&Hb[(size_t)tprev * H4 + tid]);
                acc.x = rp * h.x; acc.y = rp * h.y;
                acc.z = rp * h.z; acc.w = rp * h.w;
                ts = tprev + 1;
            }
            const int thi = s_ft[nr - 1];        // inclusive end
            int k = 0;
            int t1 = s_ft[0];
            const float* Ab = g_alphas + bT;

            for (int t = ts; t <= thi; t += 4) {
                const int i0 = t, i1 = min(t + 1, thi), i2 = min(t + 2, thi),
                          i3 = min(t + 3, thi);
                const float4 h0 = __ldg(&Hb[(size_t)i0 * H4 + tid]);
                const float4 h1 = __ldg(&Hb[(size_t)i1 * H4 + tid]);
                const float4 h2 = __ldg(&Hb[(size_t)i2 * H4 + tid]);
                const float4 h3 = __ldg(&Hb[(size_t)i3 * H4 + tid]);
                const float a0 = __ldcg(Ab + i0);
                const float a1 = __ldcg(Ab + i1);
                const float a2 = __ldcg(Ab + i2);
                const float a3 = __ldcg(Ab + i3);
                const float4 hv[4] = { h0, h1, h2, h3 };
                const float  av[4] = { a0, a1, a2, a3 };
#pragma unroll
                for (int j = 0; j < 4; j++) {
                    const int tt = t + j;
                    if (tt > thi) break;
                    const float4 h = hv[j];
                    if (tt == t1) {              // fire: close row k
                        const float d = s_dist[k];
                        float4 o;
                        o.x = fmaf(d, h.x, acc.x); o.y = fmaf(d, h.y, acc.y);
                        o.z = fmaf(d, h.z, acc.z); o.w = fmaf(d, h.w, acc.w);
                        Ob[(size_t)(r0 + k) * H4 + tid] = o;
                        const float rm = s_rem[k];
                        acc.x = rm * h.x; acc.y = rm * h.y;
                        acc.z = rm * h.z; acc.w = rm * h.w;
                        ++k;
                        t1 = (k < nr) ? s_ft[k] : -1;
                    } else {                     // interior: accumulate
                        const float a = av[j];
                        acc.x = fmaf(a, h.x, acc.x); acc.y = fmaf(a, h.y, acc.y);
                        acc.z = fmaf(a, h.z, acc.z); acc.w = fmaf(a, h.w, acc.w);
                    }
                }
            }
        }
        // zero-fill padding rows (r >= nf)
        const float4 z4 = make_float4(0.f, 0.f, 0.f, 0.f);
        for (int r = r0 + max(nr, 0); r < rlim; ++r)
            Ob[(size_t)r * H4 + tid] = z4;
    }
}

// ---------------- launch ---------------------------------------------------
extern "C" void kernel_launch(void* const* d_in, const int* in_sizes, int n_in,
                              void* d_out, int out_size)
{
    const float* hidden = (const float*)d_in[0];
    const float* conv_w = (const float*)d_in[1];
    const float* conv_b = (const float*)d_in[2];
    const float* lin_w  = (const float*)d_in[3];
    const float* lin_b  = (const float*)d_in[4];

    float* out = (float*)d_out;

    // Output layout: tuple (cif_output[B,L,H], cif_length[B], fires[B,T])
    const long long fixed = (long long)B_ + (long long)B_ * T_;
    long long rem = (long long)out_size - fixed;
    int L;
    float* out_cif;
    float* out_len;
    float* out_fires;
    if (rem > 0 && rem % ((long long)B_ * H_) == 0) {
        L = (int)(rem / ((long long)B_ * H_));
        out_cif   = out;
        out_len   = out + (size_t)B_ * L * H_;
        out_fires = out_len + B_;
    } else {
        L = (int)((long long)out_size / ((long long)B_ * H_));
        out_cif = out;
        cudaGetSymbolAddress((void**)&out_len, g_dummy_len);
        cudaGetSymbolAddress((void**)&out_fires, g_dummy_fires);
    }

    const int gblocks = (L > 0) ? (L + RPB - 1) / RPB : 0;
    init_kernel<<<4, 256>>>();
    fused_kernel<<<NS + NA + B_ * gblocks, 256>>>(hidden, conv_w, conv_b,
                                                  lin_w, lin_b,
                                                  out_cif, out_len, out_fires,
                                                  L, gblocks);
}

// round 12
// speedup vs baseline: 1.6920x; 1.6920x over previous
#include <cuda_runtime.h>
#include <math.h>

// ---------------- problem constants ----------------
#define B_ 16
#define T_ 2048
#define H_ 1024
#define H4 (H_ / 4)      // 256 float4 per row
#define BT 32            // timesteps per alphas block
#define NCHUNK (T_ / BT) // 64 alphas blocks per batch
#define NA (B_ * NCHUNK) // 1024 alphas blocks total
#define RPB 8            // output rows per gather block
#define QT 512           // scan quarter size (4 quarters)

// ---------------- device scratch (no allocations allowed) ----------------
__device__ float g_alphas[B_ * T_];
__device__ float g_dist[B_ * T_];
__device__ float g_rem[B_ * T_];
__device__ int   g_fire_t[B_ * T_];
__device__ int   g_nf[B_];
__device__ int   g_cnt[B_];       // alphas completion tickets
__device__ int   g_qnf[B_ * 4];   // per-quarter cumulative fires (+1 encoded)
__device__ int   g_sflag[B_];     // scan-done flags
__device__ float g_dummy_len[B_];
__device__ float g_dummy_fires[B_ * T_];

// ---------------- init: reset tickets/flags each call ----------------------
__global__ void init_kernel() {
    const int i = threadIdx.x;
    if (i < B_) { g_cnt[i] = 0; g_sflag[i] = 0; }
    if (i < B_ * 4) g_qnf[i] = 0;
}

// ---------------- alphas math helper ----------------
__device__ __forceinline__ float part1(float xm, float x0, float xp,
                                       float w0, float w1, float w2,
                                       float cb, float lw) {
    float v = fmaf(w0, xm, fmaf(w1, x0, fmaf(w2, xp, cb)));
    v += x0;                 // residual
    v = fmaxf(v, 0.0f);      // relu
    return lw * v;
}

// ---------------- fused kernel ---------------------------------------------
// bids [0, NA)          : alphas, batch-major (b = bid/64). The LAST finisher
//                         of each batch (ticket) runs that batch's scan,
//                         publishing progress after each 512-step quarter.
// bids [NA, NA+16*gblk) : gather, batch-major; waits until published fire
//                         count covers its row range (or scan done).
__global__ __launch_bounds__(256) void fused_kernel(
    const float* __restrict__ hidden, const float* __restrict__ conv_w,
    const float* __restrict__ conv_b, const float* __restrict__ lin_w,
    const float* __restrict__ lin_b,
    float* __restrict__ out_cif, float* __restrict__ out_len,
    float* __restrict__ out_fires, int L, int gblocks)
{
    // scan staging (idle for alphas/gather roles): 5*T_*4 = 40KB
    __shared__ float s_a[T_];
    __shared__ float s_f[T_];
    __shared__ float s_d[T_];
    __shared__ float s_r[T_];
    __shared__ int   s_t[T_];
    __shared__ int   s_misc[48];    // small int state (all roles)
    __shared__ float s_fmisc[48];   // small float state; alphas wpart = 32 floats

    const int bid = blockIdx.x;
    const int tid = threadIdx.x;

    if (bid < NA) {
        // ======================= ALPHAS (R6 body) =======================
        const int b = bid >> 6;             // batch-major: batch 0 first
        const int tstart = (bid & 63) * BT;
        const int lane = tid & 31;
        const int warp = tid >> 5;
        float (*wpart)[8] = (float (*)[8])s_fmisc;  // [4][8] = 32 floats

        const int h0 = tid * 4;
        float w0[4], w1[4], w2[4], cb[4], lw[4];
#pragma unroll
        for (int j = 0; j < 4; j++) {
            w0[j] = conv_w[(h0 + j) * 3 + 0];
            w1[j] = conv_w[(h0 + j) * 3 + 1];
            w2[j] = conv_w[(h0 + j) * 3 + 2];
            cb[j] = conv_b[h0 + j];
            lw[j] = lin_w[h0 + j];
        }
        const float lb = lin_b[0];

        const float4* Hb = (const float4*)hidden + (size_t)b * T_ * H4;
        const float4 z4 = make_float4(0.f, 0.f, 0.f, 0.f);

        float4 xm = (tstart > 0) ? Hb[(size_t)(tstart - 1) * H4 + tid] : z4;
        float4 x0 = Hb[(size_t)tstart * H4 + tid];

        for (int c = 0; c < BT / 4; ++c) {
            const int t0 = tstart + c * 4;
            float4 xA = Hb[(size_t)(t0 + 1) * H4 + tid];
            float4 xB = Hb[(size_t)(t0 + 2) * H4 + tid];
            float4 xC = Hb[(size_t)(t0 + 3) * H4 + tid];
            float4 xD = (t0 + 4 < T_) ? Hb[(size_t)(t0 + 4) * H4 + tid] : z4;

            float s[4];
            {
                const float4* P[6] = { &xm, &x0, &xA, &xB, &xC, &xD };
#pragma unroll
                for (int i = 0; i < 4; i++) {
                    const float4 a = *P[i], m = *P[i + 1], p = *P[i + 2];
                    float acc;
                    acc  = part1(a.x, m.x, p.x, w0[0], w1[0], w2[0], cb[0], lw[0]);
                    acc += part1(a.y, m.y, p.y, w0[1], w1[1], w2[1], cb[1], lw[1]);
                    acc += part1(a.z, m.z, p.z, w0[2], w1[2], w2[2], cb[2], lw[2]);
                    acc += part1(a.w, m.w, p.w, w0[3], w1[3], w2[3], cb[3], lw[3]);
                    s[i] = acc;
                }
            }
#pragma unroll
            for (int i = 0; i < 4; i++) {
#pragma unroll
                for (int off = 16; off; off >>= 1)
                    s[i] += __shfl_xor_sync(0xffffffffu, s[i], off);
            }
            if (lane == 0) {
#pragma unroll
                for (int i = 0; i < 4; i++) wpart[i][warp] = s[i];
            }
            __syncthreads();
            if (tid < 4) {
                float tot = lb;
#pragma unroll
                for (int w = 0; w < 8; w++) tot += wpart[tid][w];
                g_alphas[b * T_ + t0 + tid] = 1.0f / (1.0f + expf(-tot));
            }
            __syncthreads();
            xm = xC;
            x0 = xD;
        }

        // ---- ticket: last finisher of this batch runs the scan ----
        __threadfence();                       // release our alphas stores
        if (tid == 0)
            s_misc[0] = (atomicAdd(&g_cnt[b], 1) == NCHUNK - 1) ? 1 : 0;
        __syncthreads();
        if (s_misc[0] == 0) return;

        // ============ SCAN (quarterly flush + progress publish) =========
        const int bT = b * T_;
        {
            const float4* ap = (const float4*)(g_alphas + bT);
            for (int i = tid; i < T_ / 4; i += 256)
                ((float4*)s_a)[i] = __ldcg(ap + i);
        }
        __syncthreads();

        float integ = 0.0f;    // live only in tid 0
        int nf = 0;
        for (int qt = 0; qt < 4; ++qt) {
            if (tid == 0) {
                s_misc[2] = nf;                      // nf_start
                const int tq = qt * QT;
                for (int t = tq; t < tq + QT; t += 8) {
                    float av[8];
#pragma unroll
                    for (int j = 0; j < 8; j++) av[j] = s_a[t + j];
#pragma unroll
                    for (int j = 0; j < 8; j++) {
                        const float a = av[j];
                        const float t1 = integ + a;      // fires (pre-subtract)
                        const float dist = 1.0f - integ; // distribution completion
                        const float t2 = t1 - 1.0f;      // exact on [1,2)
                        const bool fire = (t1 >= 1.0f);
                        s_f[t + j] = t1;
                        s_d[t + j] = dist;
                        s_r[t + j] = a - dist;
                        s_t[nf] = t + j;                 // kept iff fire
                        nf += fire ? 1 : 0;
                        integ = fire ? t2 : t1;
                    }
                }
                s_misc[3] = nf;                      // nf_end
            }
            __syncthreads();
            const int tq = qt * QT;
            for (int i = tid; i < QT; i += 256) {
                out_fires[bT + tq + i] = s_f[tq + i];
                g_dist[bT + tq + i]    = s_d[tq + i];
                g_rem[bT + tq + i]     = s_r[tq + i];
            }
            for (int i = s_misc[2] + tid; i < s_misc[3]; i += 256)
                g_fire_t[bT + i] = s_t[i];
            __threadfence();                         // release quarter
            __syncthreads();
            if (tid == 0)
                atomicExch(&g_qnf[b * 4 + qt], s_misc[3] + 1);  // +1 encoding
        }
        if (tid == 0) {
            g_nf[b] = nf;
            out_len[b] = integ + (float)nf;          // == fp-sum of alphas
            __threadfence();                         // release final state
            atomicExch(&g_sflag[b], 1);
        }
    } else {
        // ======================= GATHER (R10 body) ======================
        const int idx = bid - NA;
        const int b = idx / gblocks;           // batch-major
        const int r0 = (idx - b * gblocks) * RPB;
        const int rlim = min(L, r0 + RPB);

        if (tid == 0) {
            // wait until published fires cover rlim, or scan fully done
            int nf_eff;
            while (true) {
                if (__ldcg(&g_sflag[b]) != 0) { nf_eff = __ldcg(&g_nf[b]); break; }
                int vm = __ldcg(&g_qnf[b * 4 + 0]);
                vm = max(vm, __ldcg(&g_qnf[b * 4 + 1]));
                vm = max(vm, __ldcg(&g_qnf[b * 4 + 2]));
                vm = max(vm, __ldcg(&g_qnf[b * 4 + 3]));
                if (vm - 1 >= rlim) { nf_eff = rlim; break; }  // nf >= rlim
                __nanosleep(128);
            }
            s_misc[0] = nf_eff;
        }
        __syncthreads();
        __threadfence();

        int*   s_ft   = s_misc + 8;            // [RPB]
        float* s_dist = s_fmisc;               // [RPB]
        float* s_rem  = s_fmisc + RPB;         // [RPB]

        const int nf = s_misc[0];
        const int bT = b * T_;
        const int rend = min(nf, rlim);
        const int nr = rend - r0;

        if (tid < RPB && tid < nr) {
            const int ft = __ldcg(&g_fire_t[bT + r0 + tid]);
            s_ft[tid]   = ft;
            s_dist[tid] = __ldcg(&g_dist[bT + ft]);
            s_rem[tid]  = __ldcg(&g_rem[bT + ft]);
        }
        if (tid == 0) {
            if (r0 > 0 && nr > 0) {
                const int tp = __ldcg(&g_fire_t[bT + r0 - 1]);
                s_misc[1] = tp;
                s_fmisc[2 * RPB] = __ldcg(&g_rem[bT + tp]);
            } else {
                s_misc[1] = -1;
                s_fmisc[2 * RPB] = 0.0f;
            }
        }
        __syncthreads();
        const int   tprev   = s_misc[1];
        const float remprev = s_fmisc[2 * RPB];

        const float4* Hb = (const float4*)hidden + (size_t)b * T_ * H4;
        float4* Ob = (float4*)out_cif + (size_t)b * L * H4;

        if (nr > 0) {
            float4 acc = make_float4(0.f, 0.f, 0.f, 0.f);
            int ts = 0;
            if (tprev >= 0) {
                const float rp = remprev;
                const float4 h = __ldg(&Hb[(size_t)tprev * H4 + tid]);
                acc.x = rp * h.x; acc.y = rp * h.y;
                acc.z = rp * h.z; acc.w = rp * h.w;
                ts = tprev + 1;
            }
            const int thi = s_ft[nr - 1];       // inclusive end
            int k = 0;
            int t1 = s_ft[0];
            const float* Ab = g_alphas + bT;

            for (int t = ts; t <= thi; t += 4) {
                const int i0 = t, i1 = min(t + 1, thi), i2 = min(t + 2, thi),
                          i3 = min(t + 3, thi);
                const float4 h0 = __ldg(&Hb[(size_t)i0 * H4 + tid]);
                const float4 h1 = __ldg(&Hb[(size_t)i1 * H4 + tid]);
                const float4 h2 = __ldg(&Hb[(size_t)i2 * H4 + tid]);
                const float4 h3 = __ldg(&Hb[(size_t)i3 * H4 + tid]);
                const float a0 = __ldcg(Ab + i0);
                const float a1 = __ldcg(Ab + i1);
                const float a2 = __ldcg(Ab + i2);
                const float a3 = __ldcg(Ab + i3);
                const float4 hv[4] = { h0, h1, h2, h3 };
                const float  av[4] = { a0, a1, a2, a3 };
#pragma unroll
                for (int j = 0; j < 4; j++) {
                    const int tt = t + j;
                    if (tt > thi) break;
                    const float4 h = hv[j];
                    if (tt == t1) {              // fire: close row k
                        const float d = s_dist[k];
                        float4 o;
                        o.x = fmaf(d, h.x, acc.x); o.y = fmaf(d, h.y, acc.y);
                        o.z = fmaf(d, h.z, acc.z); o.w = fmaf(d, h.w, acc.w);
                        Ob[(size_t)(r0 + k) * H4 + tid] = o;
                        const float rm = s_rem[k];
                        acc.x = rm * h.x; acc.y = rm * h.y;
                        acc.z = rm * h.z; acc.w = rm * h.w;
                        ++k;
                        t1 = (k < nr) ? s_ft[k] : -1;
                    } else {                     // interior: accumulate
                        const float a = av[j];
                        acc.x = fmaf(a, h.x, acc.x); acc.y = fmaf(a, h.y, acc.y);
                        acc.z = fmaf(a, h.z, acc.z); acc.w = fmaf(a, h.w, acc.w);
                    }
                }
            }
        }
        // zero-fill padding rows (r >= nf)
        const float4 z4 = make_float4(0.f, 0.f, 0.f, 0.f);
        for (int r = r0 + max(nr, 0); r < rlim; ++r)
            Ob[(size_t)r * H4 + tid] = z4;
    }
}

// ---------------- launch ---------------------------------------------------
extern "C" void kernel_launch(void* const* d_in, const int* in_sizes, int n_in,
                              void* d_out, int out_size)
{
    const float* hidden = (const float*)d_in[0];
    const float* conv_w = (const float*)d_in[1];
    const float* conv_b = (const float*)d_in[2];
    const float* lin_w  = (const float*)d_in[3];
    const float* lin_b  = (const float*)d_in[4];

    float* out = (float*)d_out;

    // Output layout: tuple (cif_output[B,L,H], cif_length[B], fires[B,T])
    const long long fixed = (long long)B_ + (long long)B_ * T_;
    long long rem = (long long)out_size - fixed;
    int L;
    float* out_cif;
    float* out_len;
    float* out_fires;
    if (rem > 0 && rem % ((long long)B_ * H_) == 0) {
        L = (int)(rem / ((long long)B_ * H_));
        out_cif   = out;
        out_len   = out + (size_t)B_ * L * H_;
        out_fires = out_len + B_;
    } else {
        L = (int)((long long)out_size / ((long long)B_ * H_));
        out_cif = out;
        cudaGetSymbolAddress((void**)&out_len, g_dummy_len);
        cudaGetSymbolAddress((void**)&out_fires, g_dummy_fires);
    }

    const int gblocks = (L > 0) ? (L + RPB - 1) / RPB : 0;
    init_kernel<<<1, 64>>>();
    fused_kernel<<<NA + B_ * gblocks, 256>>>(hidden, conv_w, conv_b,
                                             lin_w, lin_b,
                                             out_cif, out_len, out_fires,
                                             L, gblocks);
}

// round 13
// speedup vs baseline: 1.7548x; 1.0371x over previous
#include <cuda_runtime.h>
#include <math.h>

// ---------------- problem constants ----------------
#define B_ 16
#define T_ 2048
#define H_ 1024
#define H4 (H_ / 4)      // 256 float4 per row
#define BT 32            // timesteps per alphas block
#define NCHUNK (T_ / BT) // 64 alphas blocks per batch
#define NA (B_ * NCHUNK) // 1024 alphas blocks total
#define RPB 8            // output rows per gather block
#define QT 512           // scan quarter size (4 quarters)

// ---------------- device scratch (no allocations allowed) ----------------
__device__ float g_alphas[B_ * T_];
__device__ float g_dist[B_ * T_];
__device__ float g_rem[B_ * T_];
__device__ int   g_fire_t[B_ * T_];
__device__ int   g_nf[B_];
__device__ int   g_cnt[B_];       // alphas completion tickets
__device__ int   g_qnf[B_ * 4];   // per-quarter cumulative fires (+1 encoded)
__device__ int   g_sflag[B_];     // scan-done flags
__device__ float g_dummy_len[B_];
__device__ float g_dummy_fires[B_ * T_];

// ---------------- init: reset tickets/flags each call ----------------------
__global__ void init_kernel() {
    const int i = threadIdx.x;
    if (i < B_) { g_cnt[i] = 0; g_sflag[i] = 0; }
    if (i < B_ * 4) g_qnf[i] = 0;
}

// ---------------- alphas math helper ----------------
__device__ __forceinline__ float part1(float xm, float x0, float xp,
                                       float w0, float w1, float w2,
                                       float cb, float lw) {
    float v = fmaf(w0, xm, fmaf(w1, x0, fmaf(w2, xp, cb)));
    v += x0;                 // residual
    v = fmaxf(v, 0.0f);      // relu
    return lw * v;
}

// ---------------- fused kernel ---------------------------------------------
// bids [0, NA)          : alphas, batch-major. LAST finisher of each batch
//                         (ticket) runs that batch's scan with quarterly
//                         progress publishing.
// bids [NA, NA+16*gblk) : gather, batch-major; waits until published fire
//                         count covers its row range (or scan done).
__global__ __launch_bounds__(256) void fused_kernel(
    const float* __restrict__ hidden, const float* __restrict__ conv_w,
    const float* __restrict__ conv_b, const float* __restrict__ lin_w,
    const float* __restrict__ lin_b,
    float* __restrict__ out_cif, float* __restrict__ out_len,
    float* __restrict__ out_fires, int L, int gblocks)
{
    // scan staging (idle for alphas/gather roles): 5*T_*4 = 40KB
    __shared__ float s_a[T_];
    __shared__ float s_f[T_];
    __shared__ float s_d[T_];
    __shared__ float s_r[T_];
    __shared__ int   s_t[T_];
    __shared__ int   s_misc[48];    // small int state (all roles)
    __shared__ float s_fmisc[80];   // alphas wpart double-buffer = 64 floats

    const int bid = blockIdx.x;
    const int tid = threadIdx.x;

    if (bid < NA) {
        // ============ ALPHAS (software-pipelined, 1 barrier/iter) ========
        const int b = bid >> 6;             // batch-major: batch 0 first
        const int tstart = (bid & 63) * BT;
        const int lane = tid & 31;
        const int warp = tid >> 5;
        // double-buffered warp partials: [buf][t-in-group][warp]
        float (*wpart)[4][8] = (float (*)[4][8])s_fmisc;

        const int h0 = tid * 4;
        float w0[4], w1[4], w2[4], cb[4], lw[4];
#pragma unroll
        for (int j = 0; j < 4; j++) {
            w0[j] = conv_w[(h0 + j) * 3 + 0];
            w1[j] = conv_w[(h0 + j) * 3 + 1];
            w2[j] = conv_w[(h0 + j) * 3 + 2];
            cb[j] = conv_b[h0 + j];
            lw[j] = lin_w[h0 + j];
        }
        const float lb = lin_b[0];

        const float4* Hb = (const float4*)hidden + (size_t)b * T_ * H4;
        const float4 z4 = make_float4(0.f, 0.f, 0.f, 0.f);

        float4 xm = (tstart > 0) ? Hb[(size_t)(tstart - 1) * H4 + tid] : z4;
        float4 x0 = Hb[(size_t)tstart * H4 + tid];
        float4 xA = Hb[(size_t)(tstart + 1) * H4 + tid];
        float4 xB = Hb[(size_t)(tstart + 2) * H4 + tid];
        float4 xC = Hb[(size_t)(tstart + 3) * H4 + tid];
        float4 xD = (tstart + 4 < T_) ? Hb[(size_t)(tstart + 4) * H4 + tid] : z4;

#pragma unroll
        for (int c = 0; c < BT / 4; ++c) {
            const int t0 = tstart + c * 4;

            float s[4];
            {
                const float4* P[6] = { &xm, &x0, &xA, &xB, &xC, &xD };
#pragma unroll
                for (int i = 0; i < 4; i++) {
                    const float4 a = *P[i], m = *P[i + 1], p = *P[i + 2];
                    float acc;
                    acc  = part1(a.x, m.x, p.x, w0[0], w1[0], w2[0], cb[0], lw[0]);
                    acc += part1(a.y, m.y, p.y, w0[1], w1[1], w2[1], cb[1], lw[1]);
                    acc += part1(a.z, m.z, p.z, w0[2], w1[2], w2[2], cb[2], lw[2]);
                    acc += part1(a.w, m.w, p.w, w0[3], w1[3], w2[3], cb[3], lw[3]);
                    s[i] = acc;
                }
            }
            // rotate stencil registers, then ISSUE NEXT ITER'S LOADS now —
            // they overlap the shfl chain + barrier + epilogue below.
            xm = xC;
            x0 = xD;
            if (c < BT / 4 - 1) {
                const int tn = t0 + 4;
                xA = Hb[(size_t)(tn + 1) * H4 + tid];
                xB = Hb[(size_t)(tn + 2) * H4 + tid];
                xC = Hb[(size_t)(tn + 3) * H4 + tid];
                xD = (tn + 4 < T_) ? Hb[(size_t)(tn + 4) * H4 + tid] : z4;
            }
#pragma unroll
            for (int i = 0; i < 4; i++) {
#pragma unroll
                for (int off = 16; off; off >>= 1)
                    s[i] += __shfl_xor_sync(0xffffffffu, s[i], off);
            }
            if (lane == 0) {
#pragma unroll
                for (int i = 0; i < 4; i++) wpart[c & 1][i][warp] = s[i];
            }
            __syncthreads();          // the ONLY barrier per iter
            if (tid < 4) {
                float tot = lb;
#pragma unroll
                for (int w = 0; w < 8; w++) tot += wpart[c & 1][tid][w];
                g_alphas[b * T_ + t0 + tid] = 1.0f / (1.0f + expf(-tot));
            }
        }

        // ---- ticket: last finisher of this batch runs the scan ----
        __threadfence();                       // release our alphas stores
        if (tid == 0)
            s_misc[0] = (atomicAdd(&g_cnt[b], 1) == NCHUNK - 1) ? 1 : 0;
        __syncthreads();
        if (s_misc[0] == 0) return;

        // ============ SCAN (quarterly flush + progress publish) =========
        const int bT = b * T_;
        {
            const float4* ap = (const float4*)(g_alphas + bT);
            for (int i = tid; i < T_ / 4; i += 256)
                ((float4*)s_a)[i] = __ldcg(ap + i);
        }
        __syncthreads();

        float integ = 0.0f;    // live only in tid 0
        int nf = 0;
        for (int qt = 0; qt < 4; ++qt) {
            if (tid == 0) {
                s_misc[2] = nf;                      // nf_start
                const int tq = qt * QT;
                for (int t = tq; t < tq + QT; t += 8) {
                    float av[8];
#pragma unroll
                    for (int j = 0; j < 8; j++) av[j] = s_a[t + j];
#pragma unroll
                    for (int j = 0; j < 8; j++) {
                        const float a = av[j];
                        const float t1 = integ + a;      // fires (pre-subtract)
                        const float dist = 1.0f - integ; // distribution completion
                        const float t2 = t1 - 1.0f;      // exact on [1,2)
                        const bool fire = (t1 >= 1.0f);
                        s_f[t + j] = t1;
                        s_d[t + j] = dist;
                        s_r[t + j] = a - dist;
                        s_t[nf] = t + j;                 // kept iff fire
                        nf += fire ? 1 : 0;
                        integ = fire ? t2 : t1;
                    }
                }
                s_misc[3] = nf;                      // nf_end
            }
            __syncthreads();
            const int tq = qt * QT;
            for (int i = tid; i < QT; i += 256) {
                out_fires[bT + tq + i] = s_f[tq + i];
                g_dist[bT + tq + i]    = s_d[tq + i];
                g_rem[bT + tq + i]     = s_r[tq + i];
            }
            for (int i = s_misc[2] + tid; i < s_misc[3]; i += 256)
                g_fire_t[bT + i] = s_t[i];
            __threadfence();                         // release quarter
            __syncthreads();
            if (tid == 0)
                atomicExch(&g_qnf[b * 4 + qt], s_misc[3] + 1);  // +1 encoding
        }
        if (tid == 0) {
            g_nf[b] = nf;
            out_len[b] = integ + (float)nf;          // == fp-sum of alphas
            __threadfence();                         // release final state
            atomicExch(&g_sflag[b], 1);
        }
    } else {
        // ======================= GATHER (R12 body) ======================
        const int idx = bid - NA;
        const int b = idx / gblocks;           // batch-major
        const int r0 = (idx - b * gblocks) * RPB;
        const int rlim = min(L, r0 + RPB);

        if (tid == 0) {
            // wait until published fires cover rlim, or scan fully done
            int nf_eff;
            while (true) {
                if (__ldcg(&g_sflag[b]) != 0) { nf_eff = __ldcg(&g_nf[b]); break; }
                int vm = __ldcg(&g_qnf[b * 4 + 0]);
                vm = max(vm, __ldcg(&g_qnf[b * 4 + 1]));
                vm = max(vm, __ldcg(&g_qnf[b * 4 + 2]));
                vm = max(vm, __ldcg(&g_qnf[b * 4 + 3]));
                if (vm - 1 >= rlim) { nf_eff = rlim; break; }  // nf >= rlim
                __nanosleep(128);
            }
            s_misc[0] = nf_eff;
        }
        __syncthreads();
        __threadfence();

        int*   s_ft   = s_misc + 8;            // [RPB]
        float* s_dist = s_fmisc;               // [RPB]
        float* s_rem  = s_fmisc + RPB;         // [RPB]

        const int nf = s_misc[0];
        const int bT = b * T_;
        const int rend = min(nf, rlim);
        const int nr = rend - r0;

        if (tid < RPB && tid < nr) {
            const int ft = __ldcg(&g_fire_t[bT + r0 + tid]);
            s_ft[tid]   = ft;
            s_dist[tid] = __ldcg(&g_dist[bT + ft]);
            s_rem[tid]  = __ldcg(&g_rem[bT + ft]);
        }
        if (tid == 0) {
            if (r0 > 0 && nr > 0) {
                const int tp = __ldcg(&g_fire_t[bT + r0 - 1]);
                s_misc[1] = tp;
                s_fmisc[2 * RPB] = __ldcg(&g_rem[bT + tp]);
            } else {
                s_misc[1] = -1;
                s_fmisc[2 * RPB] = 0.0f;
            }
        }
        __syncthreads();
        const int   tprev   = s_misc[1];
        const float remprev = s_fmisc[2 * RPB];

        const float4* Hb = (const float4*)hidden + (size_t)b * T_ * H4;
        float4* Ob = (float4*)out_cif + (size_t)b * L * H4;

        if (nr > 0) {
            float4 acc = make_float4(0.f, 0.f, 0.f, 0.f);
            int ts = 0;
            if (tprev >= 0) {
                const float rp = remprev;
                const float4 h = __ldg(&Hb[(size_t)tprev * H4 + tid]);
                acc.x = rp * h.x; acc.y = rp * h.y;
                acc.z = rp * h.z; acc.w = rp * h.w;
                ts = tprev + 1;
            }
            const int thi = s_ft[nr - 1];       // inclusive end
            int k = 0;
            int t1 = s_ft[0];
            const float* Ab = g_alphas + bT;

            for (int t = ts; t <= thi; t += 4) {
                const int i0 = t, i1 = min(t + 1, thi), i2 = min(t + 2, thi),
                          i3 = min(t + 3, thi);
                const float4 h0 = __ldg(&Hb[(size_t)i0 * H4 + tid]);
                const float4 h1 = __ldg(&Hb[(size_t)i1 * H4 + tid]);
                const float4 h2 = __ldg(&Hb[(size_t)i2 * H4 + tid]);
                const float4 h3 = __ldg(&Hb[(size_t)i3 * H4 + tid]);
                const float a0 = __ldcg(Ab + i0);
                const float a1 = __ldcg(Ab + i1);
                const float a2 = __ldcg(Ab + i2);
                const float a3 = __ldcg(Ab + i3);
                const float4 hv[4] = { h0, h1, h2, h3 };
                const float  av[4] = { a0, a1, a2, a3 };
#pragma unroll
                for (int j = 0; j < 4; j++) {
                    const int tt = t + j;
                    if (tt > thi) break;
                    const float4 h = hv[j];
                    if (tt == t1) {              // fire: close row k
                        const float d = s_dist[k];
                        float4 o;
                        o.x = fmaf(d, h.x, acc.x); o.y = fmaf(d, h.y, acc.y);
                        o.z = fmaf(d, h.z, acc.z); o.w = fmaf(d, h.w, acc.w);
                        Ob[(size_t)(r0 + k) * H4 + tid] = o;
                        const float rm = s_rem[k];
                        acc.x = rm * h.x; acc.y = rm * h.y;
                        acc.z = rm * h.z; acc.w = rm * h.w;
                        ++k;
                        t1 = (k < nr) ? s_ft[k] : -1;
                    } else {                     // interior: accumulate
                        const float a = av[j];
                        acc.x = fmaf(a, h.x, acc.x); acc.y = fmaf(a, h.y, acc.y);
                        acc.z = fmaf(a, h.z, acc.z); acc.w = fmaf(a, h.w, acc.w);
                    }
                }
            }
        }
        // zero-fill padding rows (r >= nf)
        const float4 z4 = make_float4(0.f, 0.f, 0.f, 0.f);
        for (int r = r0 + max(nr, 0); r < rlim; ++r)
            Ob[(size_t)r * H4 + tid] = z4;
    }
}

// ---------------- launch ---------------------------------------------------
extern "C" void kernel_launch(void* const* d_in, const int* in_sizes, int n_in,
                              void* d_out, int out_size)
{
    const float* hidden = (const float*)d_in[0];
    const float* conv_w = (const float*)d_in[1];
    const float* conv_b = (const float*)d_in[2];
    const float* lin_w  = (const float*)d_in[3];
    const float* lin_b  = (const float*)d_in[4];

    float* out = (float*)d_out;

    // Output layout: tuple (cif_output[B,L,H], cif_length[B], fires[B,T])
    const long long fixed = (long long)B_ + (long long)B_ * T_;
    long long rem = (long long)out_size - fixed;
    int L;
    float* out_cif;
    float* out_len;
    float* out_fires;
    if (rem > 0 && rem % ((long long)B_ * H_) == 0) {
        L = (int)(rem / ((long long)B_ * H_));
        out_cif   = out;
        out_len   = out + (size_t)B_ * L * H_;
        out_fires = out_len + B_;
    } else {
        L = (int)((long long)out_size / ((long long)B_ * H_));
        out_cif = out;
        cudaGetSymbolAddress((void**)&out_len, g_dummy_len);
        cudaGetSymbolAddress((void**)&out_fires, g_dummy_fires);
    }

    const int gblocks = (L > 0) ? (L + RPB - 1) / RPB : 0;
    init_kernel<<<1, 64>>>();
    fused_kernel<<<NA + B_ * gblocks, 256>>>(hidden, conv_w, conv_b,
                                             lin_w, lin_b,
                                             out_cif, out_len, out_fires,
                                             L, gblocks);
}